// round 7
// baseline (speedup 1.0000x reference)
#include <cuda_runtime.h>
#include <math.h>

#define Nn 50000
#define Ee 800000
#define Gg 64
#define Rr 3

// ---------------- scratch (static device globals; no allocation) ----------------
__device__ float  d_A[(size_t)Nn * 1024];   // [N, 4*din] combined [h | agg0 | agg1 | agg2]
__device__ float  d_h[(size_t)Nn * 256];    // layer input (stride = din)
__device__ float  d_y[(size_t)Nn * 256];    // pre-BN layer output (stride = dout)
__device__ float  d_invcnt[Rr * Nn];        // 1/max(cnt,1) per (relation,dst)
__device__ double d_stat[512];              // col sums [0..255], col sumsq [256..511]
__device__ float  d_scale[256];             // BN fused scale
__device__ float  d_shift[256];             // BN fused shift
__device__ float  d_pool[Gg * 256];
__device__ float  d_poolcnt[Gg];

// ---------------- trivial kernels ----------------
__global__ void copy_x_k(const float* __restrict__ x) {
    int i = blockIdx.x * blockDim.x + threadIdx.x;
    if (i < Nn * 128 / 4) ((float4*)d_h)[i] = ((const float4*)x)[i];
}

__global__ void zero_cnt_k() {
    int i = blockIdx.x * blockDim.x + threadIdx.x;
    if (i < Rr * Nn) d_invcnt[i] = 0.0f;
}

__global__ void count_k(const int* __restrict__ et, const int* __restrict__ dst) {
    int e = blockIdx.x * blockDim.x + threadIdx.x;
    if (e < Ee) atomicAdd(&d_invcnt[et[e] * Nn + dst[e]], 1.0f);
}

__global__ void inv_k() {
    int i = blockIdx.x * blockDim.x + threadIdx.x;
    if (i < Rr * Nn) d_invcnt[i] = 1.0f / fmaxf(d_invcnt[i], 1.0f);
}

// A = [h | 0 | 0 | 0]
__global__ void fillA_k(int din, int K) {
    int idx = blockIdx.x * blockDim.x + threadIdx.x;
    int K4 = K >> 2;
    if (idx >= Nn * K4) return;
    int n = idx / K4;
    int k = (idx - n * K4) << 2;
    float4 v = make_float4(0.f, 0.f, 0.f, 0.f);
    if (k < din) v = *(const float4*)&d_h[(size_t)n * din + k];
    *(float4*)&d_A[(size_t)n * K + k] = v;
}

// per-edge scaled scatter: A[dst, din + r*din + c] += h[src, c] * invcnt[r,dst]
__global__ void scatter_k(const int* __restrict__ src, const int* __restrict__ dst,
                          const int* __restrict__ et, int din, int K) {
    int gt = blockIdx.x * blockDim.x + threadIdx.x;
    int e = gt >> 5, lane = gt & 31;
    if (e >= Ee) return;
    int s = src[e], d = dst[e], r = et[e];
    float sc = d_invcnt[r * Nn + d];
    const float* hs = d_h + (size_t)s * din;
    float* Ar = d_A + (size_t)d * K + din + r * din;
    int nq = din >> 2;
    for (int q = lane; q < nq; q += 32) {
        float4 v = *(const float4*)(hs + (q << 2));
        atomicAdd(Ar + (q << 2) + 0, v.x * sc);
        atomicAdd(Ar + (q << 2) + 1, v.y * sc);
        atomicAdd(Ar + (q << 2) + 2, v.z * sc);
        atomicAdd(Ar + (q << 2) + 3, v.w * sc);
    }
}

// ---------------- main GEMM: Y[N,dout] = A[N,K] @ B(K,dout) + bias ----------------
// B(k,j) = (k < din) ? Rw[k,j] : W[(k-din), j]  (W is [R*din, dout] contiguous)
// 128x128x16 tile, 256 threads, 8x8 micro-tile, M-paired fma.rn.f32x2.
__global__ void __launch_bounds__(256) gemm_k(
    const float* __restrict__ Rw, const float* __restrict__ Wr,
    const float* __restrict__ bias, int K, int din, int dout)
{
    __shared__ float As[16][128];
    __shared__ float Bs[16][128];
    int t  = threadIdx.x;
    int tm = t >> 4, tn = t & 15;
    int mbase = blockIdx.x * 128;
    int nbase = blockIdx.y * 128;

    // A staging: thread loads float4 along k for rows a_m and a_m+64
    int a_m  = t >> 2;
    int a_k4 = (t & 3) << 2;
    int arow0 = mbase + a_m;
    int arow1 = arow0 + 64;
    // B staging: thread loads float4 along j for k rows b_k and b_k+8
    int b_j = (t & 31) << 2;
    int b_k = t >> 5;
    int jg  = nbase + b_j;

    unsigned long long acc[4][8];
#pragma unroll
    for (int i = 0; i < 4; i++)
#pragma unroll
        for (int j = 0; j < 8; j++) acc[i][j] = 0ull;

    int ktiles = K >> 4;
    for (int kt = 0; kt < ktiles; kt++) {
        int k0 = kt << 4;
        float4 a0 = make_float4(0.f,0.f,0.f,0.f), a1 = a0;
        if (arow0 < Nn) a0 = *(const float4*)&d_A[(size_t)arow0 * K + k0 + a_k4];
        if (arow1 < Nn) a1 = *(const float4*)&d_A[(size_t)arow1 * K + k0 + a_k4];
        float4 b0 = make_float4(0.f,0.f,0.f,0.f), b1 = b0;
        if (jg < dout) {
            int kg0 = k0 + b_k;
            const float* p0 = (kg0 < din) ? (Rw + (size_t)kg0 * dout)
                                          : (Wr + (size_t)(kg0 - din) * dout);
            b0 = *(const float4*)(p0 + jg);
            int kg1 = kg0 + 8;
            const float* p1 = (kg1 < din) ? (Rw + (size_t)kg1 * dout)
                                          : (Wr + (size_t)(kg1 - din) * dout);
            b1 = *(const float4*)(p1 + jg);
        }
        __syncthreads();
        As[a_k4 + 0][a_m]      = a0.x; As[a_k4 + 1][a_m]      = a0.y;
        As[a_k4 + 2][a_m]      = a0.z; As[a_k4 + 3][a_m]      = a0.w;
        As[a_k4 + 0][a_m + 64] = a1.x; As[a_k4 + 1][a_m + 64] = a1.y;
        As[a_k4 + 2][a_m + 64] = a1.z; As[a_k4 + 3][a_m + 64] = a1.w;
        *(float4*)&Bs[b_k][b_j]     = b0;
        *(float4*)&Bs[b_k + 8][b_j] = b1;
        __syncthreads();

#pragma unroll
        for (int kk = 0; kk < 16; kk++) {
            ulonglong2 av0 = *(const ulonglong2*)&As[kk][tm * 4];
            ulonglong2 av1 = *(const ulonglong2*)&As[kk][tm * 4 + 64];
            unsigned long long a2[4] = { av0.x, av0.y, av1.x, av1.y };
            float4 bq0 = *(const float4*)&Bs[kk][tn * 4];
            float4 bq1 = *(const float4*)&Bs[kk][tn * 4 + 64];
            float bf[8] = { bq0.x, bq0.y, bq0.z, bq0.w, bq1.x, bq1.y, bq1.z, bq1.w };
            unsigned long long bd[8];
#pragma unroll
            for (int j = 0; j < 8; j++) {
                unsigned int u = __float_as_uint(bf[j]);
                asm("mov.b64 %0, {%1, %2};" : "=l"(bd[j]) : "r"(u), "r"(u));
            }
#pragma unroll
            for (int i = 0; i < 4; i++)
#pragma unroll
                for (int j = 0; j < 8; j++)
                    asm("fma.rn.f32x2 %0, %1, %2, %0;"
                        : "+l"(acc[i][j]) : "l"(a2[i]), "l"(bd[j]));
        }
    }

    // epilogue
    int c0 = nbase + tn * 4;
    int c1 = c0 + 64;
    float4 bias0 = make_float4(0.f,0.f,0.f,0.f), bias1 = bias0;
    if (c0 < dout) bias0 = *(const float4*)&bias[c0];
    if (c1 < dout) bias1 = *(const float4*)&bias[c1];

#pragma unroll
    for (int i = 0; i < 4; i++) {
        int p = mbase + ((i >> 1) << 6) + tm * 4 + ((i & 1) << 1); // rows p, p+1
        float v0[8], v1[8];
#pragma unroll
        for (int j = 0; j < 8; j++) {
            unsigned int ul, uh;
            asm("mov.b64 {%0, %1}, %2;" : "=r"(ul), "=r"(uh) : "l"(acc[i][j]));
            v0[j] = __uint_as_float(ul);
            v1[j] = __uint_as_float(uh);
        }
        if (p < Nn) {
            if (c0 < dout) {
                float4 o = make_float4(v0[0]+bias0.x, v0[1]+bias0.y, v0[2]+bias0.z, v0[3]+bias0.w);
                *(float4*)&d_y[(size_t)p * dout + c0] = o;
            }
            if (c1 < dout) {
                float4 o = make_float4(v0[4]+bias1.x, v0[5]+bias1.y, v0[6]+bias1.z, v0[7]+bias1.w);
                *(float4*)&d_y[(size_t)p * dout + c1] = o;
            }
        }
        if (p + 1 < Nn) {
            if (c0 < dout) {
                float4 o = make_float4(v1[0]+bias0.x, v1[1]+bias0.y, v1[2]+bias0.z, v1[3]+bias0.w);
                *(float4*)&d_y[(size_t)(p + 1) * dout + c0] = o;
            }
            if (c1 < dout) {
                float4 o = make_float4(v1[4]+bias1.x, v1[5]+bias1.y, v1[6]+bias1.z, v1[7]+bias1.w);
                *(float4*)&d_y[(size_t)(p + 1) * dout + c1] = o;
            }
        }
    }
}

// ---------------- BatchNorm (training mode) ----------------
__global__ void zero_stat_k() {
    int i = threadIdx.x;
    if (i < 512) d_stat[i] = 0.0;
}

__global__ void stats_k(int dout) {
    int c = threadIdx.x;
    int rows = (Nn + gridDim.x - 1) / gridDim.x;
    int r0 = blockIdx.x * rows;
    int r1 = min(Nn, r0 + rows);
    if (c >= dout) return;
    float s = 0.f, q = 0.f;
    for (int r = r0; r < r1; r++) {
        float v = d_y[(size_t)r * dout + c];
        s += v; q += v * v;
    }
    atomicAdd(&d_stat[c], (double)s);
    atomicAdd(&d_stat[256 + c], (double)q);
}

__global__ void prep_bn_k(const float* __restrict__ gamma, const float* __restrict__ beta, int dout) {
    int c = threadIdx.x;
    if (c >= dout) return;
    double mu  = d_stat[c] / (double)Nn;
    double var = d_stat[256 + c] / (double)Nn - mu * mu;
    float rs = rsqrtf(fmaxf((float)var, 0.f) + 1e-5f);
    float sc = rs * gamma[c];
    d_scale[c] = sc;
    d_shift[c] = beta[c] - (float)mu * sc;
}

__global__ void norm_k(int dout) {
    int idx4 = blockIdx.x * blockDim.x + threadIdx.x;
    int tot = (Nn * dout) >> 2;
    if (idx4 >= tot) return;
    int c = (idx4 << 2) % dout;  // dout % 4 == 0
    float4 y  = ((const float4*)d_y)[idx4];
    float4 sc = *(const float4*)&d_scale[c];
    float4 sh = *(const float4*)&d_shift[c];
    float4 o = make_float4(y.x * sc.x + sh.x, y.y * sc.y + sh.y,
                           y.z * sc.z + sh.z, y.w * sc.w + sh.w);
    ((float4*)d_h)[idx4] = o;
}

// ---------------- pooling + MLP head ----------------
__global__ void zero_pool_k() {
    int i = blockIdx.x * blockDim.x + threadIdx.x;
    if (i < Gg * 256) d_pool[i] = 0.f;
    if (i < Gg) d_poolcnt[i] = 0.f;
}

__global__ void pool_k(const int* __restrict__ batch) {
    int gt = blockIdx.x * blockDim.x + threadIdx.x;
    int n = gt >> 5, lane = gt & 31;
    if (n >= Nn) return;
    int g = batch[n];
    const float* hr = d_h + (size_t)n * 256;
#pragma unroll
    for (int q = lane; q < 64; q += 32) {
        float4 v = *(const float4*)(hr + (q << 2));
        atomicAdd(&d_pool[g * 256 + (q << 2) + 0], v.x);
        atomicAdd(&d_pool[g * 256 + (q << 2) + 1], v.y);
        atomicAdd(&d_pool[g * 256 + (q << 2) + 2], v.z);
        atomicAdd(&d_pool[g * 256 + (q << 2) + 3], v.w);
    }
    if (lane == 0) atomicAdd(&d_poolcnt[g], 1.0f);
}

__global__ void mlp_k(const float* __restrict__ meta,
                      const float* __restrict__ l1w, const float* __restrict__ l1b,
                      const float* __restrict__ l2w, const float* __restrict__ l2b,
                      float* __restrict__ out) {
    int g = blockIdx.x;
    int t = threadIdx.x;  // 128
    __shared__ float feat[294];
    __shared__ float red[128];
    float icnt = 1.0f / fmaxf(d_poolcnt[g], 1.0f);
    for (int c = t; c < 294; c += 128)
        feat[c] = (c < 256) ? d_pool[g * 256 + c] * icnt : meta[g * 38 + (c - 256)];
    __syncthreads();
    float val = 0.f;
    if (t < 100) {
        float a = l1b[t];
        for (int i = 0; i < 294; i++) a += feat[i] * l1w[i * 100 + t];
        val = a * l2w[t];
    }
    red[t] = val;
    __syncthreads();
    for (int s = 64; s > 0; s >>= 1) {
        if (t < s) red[t] += red[t + s];
        __syncthreads();
    }
    if (t == 0) out[g] = red[0] + l2b[0];
}

// ---------------- host launcher (graph-capturable, alloc-free) ----------------
extern "C" void kernel_launch(void* const* d_in, const int* in_sizes, int n_in,
                              void* d_out, int out_size) {
    const float* x    = (const float*)d_in[0];
    const int*   eidx = (const int*)d_in[2];
    const int*   srcp = eidx;
    const int*   dstp = eidx + Ee;
    const int*   et   = (const int*)d_in[3];
    const float* meta = (const float*)d_in[4];
    const int*   bat  = (const int*)d_in[5];

    copy_x_k<<<(Nn * 128 / 4 + 255) / 256, 256>>>(x);
    zero_cnt_k<<<(Rr * Nn + 255) / 256, 256>>>();
    count_k<<<(Ee + 255) / 256, 256>>>(et, dstp);
    inv_k<<<(Rr * Nn + 255) / 256, 256>>>();

    const int dins[4]  = {128, 100, 256, 256};
    const int douts[4] = {100, 256, 256, 256};
    for (int l = 0; l < 4; l++) {
        int din = dins[l], dout = douts[l], K = 4 * din;
        const float* W   = (const float*)d_in[6 + 5 * l];
        const float* Rw  = (const float*)d_in[7 + 5 * l];
        const float* bia = (const float*)d_in[8 + 5 * l];
        const float* gam = (const float*)d_in[9 + 5 * l];
        const float* bet = (const float*)d_in[10 + 5 * l];

        fillA_k<<<(Nn * (K / 4) + 255) / 256, 256>>>(din, K);
        scatter_k<<<(Ee * 32 + 255) / 256, 256>>>(srcp, dstp, et, din, K);
        gemm_k<<<dim3((Nn + 127) / 128, (dout + 127) / 128), 256>>>(Rw, W, bia, K, din, dout);
        zero_stat_k<<<1, 512>>>();
        stats_k<<<512, 256>>>(dout);
        prep_bn_k<<<1, 256>>>(gam, bet, dout);
        norm_k<<<((Nn * dout) / 4 + 255) / 256, 256>>>(dout);
    }

    zero_pool_k<<<(Gg * 256 + 255) / 256, 256>>>();
    pool_k<<<(Nn * 32 + 255) / 256, 256>>>(bat);
    mlp_k<<<Gg, 128>>>(meta, (const float*)d_in[26], (const float*)d_in[27],
                       (const float*)d_in[28], (const float*)d_in[29], (float*)d_out);
}

// round 13
// speedup vs baseline: 1.5822x; 1.5822x over previous
#include <cuda_runtime.h>
#include <math.h>
#include <stdint.h>

#define Nn 50000
#define Ee 800000
#define Gg 64
#define Rr 3
#define SEGS (Rr * Nn)            // 150000 (relation, dst) segments
#define SCAN_BLKS 148             // 148 * 1024 >= SEGS+1

// ---------------- scratch (static device globals; no allocation) ----------------
__device__ __align__(128) float  d_A[(size_t)Nn * 1024];   // [N, K] combined [h | agg0 | agg1 | agg2]
__device__ __align__(128) float  d_h[(size_t)Nn * 256];    // layer input, post-BN (stride = din)
__device__ __align__(128) float  d_y[(size_t)Nn * 256];    // pre-BN layer output (stride = dout)
__device__ double d_stat[512];              // col sums [0..255], col sumsq [256..511]
__device__ float  d_scale[256];             // BN fused scale
__device__ float  d_shift[256];             // BN fused shift
__device__ float  d_pool[Gg * 256];
__device__ float  d_poolcnt[Gg];
// CSR structures (built once per call from edge_index/edge_type)
__device__ int    d_rowptr[SEGS + 1];
__device__ int    d_blk[SCAN_BLKS];
__device__ int    d_cur[SEGS];
__device__ int    d_col[Ee];

// ---------------- CSR build ----------------
__global__ void zero_ptr_k() {
    int i = blockIdx.x * blockDim.x + threadIdx.x;
    if (i <= SEGS) d_rowptr[i] = 0;
}

__global__ void count_k(const int* __restrict__ et, const int* __restrict__ dst) {
    int e = blockIdx.x * blockDim.x + threadIdx.x;
    if (e < Ee) atomicAdd(&d_rowptr[et[e] * Nn + dst[e] + 1], 1);
}

// inclusive scan over d_rowptr[0..SEGS]: pass 1 — per-block (1024 elems) scan
__global__ void scan1_k() {
    __shared__ int sh[256];
    int blk = blockIdx.x, t = threadIdx.x;
    int base = blk * 1024 + t * 4;
    int v[4];
#pragma unroll
    for (int i = 0; i < 4; i++) {
        int idx = base + i;
        v[i] = (idx <= SEGS) ? d_rowptr[idx] : 0;
    }
    v[1] += v[0]; v[2] += v[1]; v[3] += v[2];
    int tsum = v[3];
    sh[t] = tsum;
    __syncthreads();
    for (int off = 1; off < 256; off <<= 1) {
        int x = (t >= off) ? sh[t - off] : 0;
        __syncthreads();
        sh[t] += x;
        __syncthreads();
    }
    int off0 = sh[t] - tsum;
#pragma unroll
    for (int i = 0; i < 4; i++) {
        int idx = base + i;
        if (idx <= SEGS) d_rowptr[idx] = v[i] + off0;
    }
    if (t == 255) d_blk[blk] = sh[255];
}

// pass 2 — exclusive scan of block sums (single block)
__global__ void scan2_k() {
    __shared__ int sh[SCAN_BLKS];
    int t = threadIdx.x;
    if (t < SCAN_BLKS) sh[t] = d_blk[t];
    __syncthreads();
    if (t == 0) {
        int acc = 0;
        for (int b = 0; b < SCAN_BLKS; b++) { int x = sh[b]; sh[b] = acc; acc += x; }
    }
    __syncthreads();
    if (t < SCAN_BLKS) d_blk[t] = sh[t];
}

// pass 3 — add block offsets
__global__ void scan3_k() {
    int blk = blockIdx.x, t = threadIdx.x;
    int add = d_blk[blk];
    if (add == 0) return;
    int base = blk * 1024 + t * 4;
#pragma unroll
    for (int i = 0; i < 4; i++) {
        int idx = base + i;
        if (idx <= SEGS) d_rowptr[idx] += add;
    }
}

__global__ void cursor_k() {
    int i = blockIdx.x * blockDim.x + threadIdx.x;
    if (i < SEGS) d_cur[i] = d_rowptr[i];
}

__global__ void fillcol_k(const int* __restrict__ src, const int* __restrict__ dst,
                          const int* __restrict__ et) {
    int e = blockIdx.x * blockDim.x + threadIdx.x;
    if (e >= Ee) return;
    int seg = et[e] * Nn + dst[e];
    int pos = atomicAdd(&d_cur[seg], 1);
    d_col[pos] = src[e];
}

// ---------------- misc copies ----------------
__global__ void copy_x_k(const float* __restrict__ x) {
    int i = blockIdx.x * blockDim.x + threadIdx.x;
    if (i < Nn * 128 / 4) ((float4*)d_h)[i] = ((const float4*)x)[i];
}

// A[n, 0:din] = d_h[n] (copy-only; agg region fully written by gather)
__global__ void fillh_k(int din, int K) {
    int idx = blockIdx.x * blockDim.x + threadIdx.x;
    int din4 = din >> 2;
    if (idx >= Nn * din4) return;
    int n = idx / din4;
    int c = (idx - n * din4) << 2;
    float4 v = *(const float4*)&d_h[(size_t)n * din + c];
    *(float4*)&d_A[(size_t)n * K + c] = v;
}

// ---------------- gather: warp per (relation,dst) segment ----------------
// A[dst, din + r*din + c] = mean over CSR segment of d_h[src, c]  (0 if empty)
__global__ void gather_k(int din, int K) {
    int gt = blockIdx.x * blockDim.x + threadIdx.x;
    int seg = gt >> 5, lane = gt & 31;
    if (seg >= SEGS) return;
    int r = seg / Nn;
    int dstn = seg - r * Nn;
    int beg = d_rowptr[seg];
    int end = d_rowptr[seg + 1];
    int len = end - beg;
    int din4 = din >> 2;
    int q0 = lane, q1 = lane + 32;
    bool h0 = q0 < din4, h1 = q1 < din4;

    float4 acc0 = make_float4(0.f, 0.f, 0.f, 0.f);
    float4 acc1 = acc0;
    for (int e = beg; e < end; e++) {
        int s = d_col[e];
        const float4* hp = (const float4*)(d_h + (size_t)s * din);
        if (h0) {
            float4 v = hp[q0];
            acc0.x += v.x; acc0.y += v.y; acc0.z += v.z; acc0.w += v.w;
        }
        if (h1) {
            float4 v = hp[q1];
            acc1.x += v.x; acc1.y += v.y; acc1.z += v.z; acc1.w += v.w;
        }
    }
    float inv = (len > 0) ? (1.0f / (float)len) : 0.0f;
    float* Ar = d_A + (size_t)dstn * K + din + r * din;
    if (h0) {
        int c = q0 << 2;
        *(float4*)(Ar + c) = make_float4(acc0.x * inv, acc0.y * inv,
                                         acc0.z * inv, acc0.w * inv);
    }
    if (h1) {
        int c = q1 << 2;
        *(float4*)(Ar + c) = make_float4(acc1.x * inv, acc1.y * inv,
                                         acc1.z * inv, acc1.w * inv);
    }
}

// ---------------- main GEMM: Y[N,dout] = A[N,K] @ B(K,dout) + bias ----------------
// (byte-identical to the round-7 passing kernel)
__global__ void __launch_bounds__(256) gemm_k(
    const float* __restrict__ Rw, const float* __restrict__ Wr,
    const float* __restrict__ bias, int K, int din, int dout)
{
    __shared__ float As[16][128];
    __shared__ float Bs[16][128];
    int t  = threadIdx.x;
    int tm = t >> 4, tn = t & 15;
    int mbase = blockIdx.x * 128;
    int nbase = blockIdx.y * 128;

    int a_m  = t >> 2;
    int a_k4 = (t & 3) << 2;
    int arow0 = mbase + a_m;
    int arow1 = arow0 + 64;
    int b_j = (t & 31) << 2;
    int b_k = t >> 5;
    int jg  = nbase + b_j;

    unsigned long long acc[4][8];
#pragma unroll
    for (int i = 0; i < 4; i++)
#pragma unroll
        for (int j = 0; j < 8; j++) acc[i][j] = 0ull;

    int ktiles = K >> 4;
    for (int kt = 0; kt < ktiles; kt++) {
        int k0 = kt << 4;
        float4 a0 = make_float4(0.f,0.f,0.f,0.f), a1 = a0;
        if (arow0 < Nn) a0 = *(const float4*)&d_A[(size_t)arow0 * K + k0 + a_k4];
        if (arow1 < Nn) a1 = *(const float4*)&d_A[(size_t)arow1 * K + k0 + a_k4];
        float4 b0 = make_float4(0.f,0.f,0.f,0.f), b1 = b0;
        if (jg < dout) {
            int kg0 = k0 + b_k;
            const float* p0 = (kg0 < din) ? (Rw + (size_t)kg0 * dout)
                                          : (Wr + (size_t)(kg0 - din) * dout);
            b0 = *(const float4*)(p0 + jg);
            int kg1 = kg0 + 8;
            const float* p1 = (kg1 < din) ? (Rw + (size_t)kg1 * dout)
                                          : (Wr + (size_t)(kg1 - din) * dout);
            b1 = *(const float4*)(p1 + jg);
        }
        __syncthreads();
        As[a_k4 + 0][a_m]      = a0.x; As[a_k4 + 1][a_m]      = a0.y;
        As[a_k4 + 2][a_m]      = a0.z; As[a_k4 + 3][a_m]      = a0.w;
        As[a_k4 + 0][a_m + 64] = a1.x; As[a_k4 + 1][a_m + 64] = a1.y;
        As[a_k4 + 2][a_m + 64] = a1.z; As[a_k4 + 3][a_m + 64] = a1.w;
        *(float4*)&Bs[b_k][b_j]     = b0;
        *(float4*)&Bs[b_k + 8][b_j] = b1;
        __syncthreads();

#pragma unroll
        for (int kk = 0; kk < 16; kk++) {
            ulonglong2 av0 = *(const ulonglong2*)&As[kk][tm * 4];
            ulonglong2 av1 = *(const ulonglong2*)&As[kk][tm * 4 + 64];
            unsigned long long a2[4] = { av0.x, av0.y, av1.x, av1.y };
            float4 bq0 = *(const float4*)&Bs[kk][tn * 4];
            float4 bq1 = *(const float4*)&Bs[kk][tn * 4 + 64];
            float bf[8] = { bq0.x, bq0.y, bq0.z, bq0.w, bq1.x, bq1.y, bq1.z, bq1.w };
            unsigned long long bd[8];
#pragma unroll
            for (int j = 0; j < 8; j++) {
                unsigned int u = __float_as_uint(bf[j]);
                asm("mov.b64 %0, {%1, %2};" : "=l"(bd[j]) : "r"(u), "r"(u));
            }
#pragma unroll
            for (int i = 0; i < 4; i++)
#pragma unroll
                for (int j = 0; j < 8; j++)
                    asm("fma.rn.f32x2 %0, %1, %2, %0;"
                        : "+l"(acc[i][j]) : "l"(a2[i]), "l"(bd[j]));
        }
    }

    int c0 = nbase + tn * 4;
    int c1 = c0 + 64;
    float4 bias0 = make_float4(0.f,0.f,0.f,0.f), bias1 = bias0;
    if (c0 < dout) bias0 = *(const float4*)&bias[c0];
    if (c1 < dout) bias1 = *(const float4*)&bias[c1];

#pragma unroll
    for (int i = 0; i < 4; i++) {
        int p = mbase + ((i >> 1) << 6) + tm * 4 + ((i & 1) << 1);
        float v0[8], v1[8];
#pragma unroll
        for (int j = 0; j < 8; j++) {
            unsigned int ul, uh;
            asm("mov.b64 {%0, %1}, %2;" : "=r"(ul), "=r"(uh) : "l"(acc[i][j]));
            v0[j] = __uint_as_float(ul);
            v1[j] = __uint_as_float(uh);
        }
        if (p < Nn) {
            if (c0 < dout) {
                float4 o = make_float4(v0[0]+bias0.x, v0[1]+bias0.y, v0[2]+bias0.z, v0[3]+bias0.w);
                *(float4*)&d_y[(size_t)p * dout + c0] = o;
            }
            if (c1 < dout) {
                float4 o = make_float4(v0[4]+bias1.x, v0[5]+bias1.y, v0[6]+bias1.z, v0[7]+bias1.w);
                *(float4*)&d_y[(size_t)p * dout + c1] = o;
            }
        }
        if (p + 1 < Nn) {
            if (c0 < dout) {
                float4 o = make_float4(v1[0]+bias0.x, v1[1]+bias0.y, v1[2]+bias0.z, v1[3]+bias0.w);
                *(float4*)&d_y[(size_t)(p + 1) * dout + c0] = o;
            }
            if (c1 < dout) {
                float4 o = make_float4(v1[4]+bias1.x, v1[5]+bias1.y, v1[6]+bias1.z, v1[7]+bias1.w);
                *(float4*)&d_y[(size_t)(p + 1) * dout + c1] = o;
            }
        }
    }
}

// ---------------- BatchNorm (training mode; round-7 proven) ----------------
__global__ void zero_stat_k() {
    int i = threadIdx.x;
    if (i < 512) d_stat[i] = 0.0;
}

__global__ void stats_k(int dout) {
    int c = threadIdx.x;
    int rows = (Nn + gridDim.x - 1) / gridDim.x;
    int r0 = blockIdx.x * rows;
    int r1 = min(Nn, r0 + rows);
    if (c >= dout) return;
    float s = 0.f, q = 0.f;
    for (int r = r0; r < r1; r++) {
        float v = d_y[(size_t)r * dout + c];
        s += v; q += v * v;
    }
    atomicAdd(&d_stat[c], (double)s);
    atomicAdd(&d_stat[256 + c], (double)q);
}

__global__ void prep_bn_k(const float* __restrict__ gamma, const float* __restrict__ beta, int dout) {
    int c = threadIdx.x;
    if (c >= dout) return;
    double mu  = d_stat[c] / (double)Nn;
    double var = d_stat[256 + c] / (double)Nn - mu * mu;
    float rs = rsqrtf(fmaxf((float)var, 0.f) + 1e-5f);
    float sc = rs * gamma[c];
    d_scale[c] = sc;
    d_shift[c] = beta[c] - (float)mu * sc;
}

__global__ void norm_k(int dout) {
    int idx4 = blockIdx.x * blockDim.x + threadIdx.x;
    int tot = (Nn * dout) >> 2;
    if (idx4 >= tot) return;
    int c = (idx4 << 2) % dout;  // dout % 4 == 0
    float4 y  = ((const float4*)d_y)[idx4];
    float4 sc = *(const float4*)&d_scale[c];
    float4 sh = *(const float4*)&d_shift[c];
    ((float4*)d_h)[idx4] = make_float4(y.x * sc.x + sh.x, y.y * sc.y + sh.y,
                                       y.z * sc.z + sh.z, y.w * sc.w + sh.w);
}

// ---------------- pooling + MLP head (round-7 proven) ----------------
__global__ void zero_pool_k() {
    int i = blockIdx.x * blockDim.x + threadIdx.x;
    if (i < Gg * 256) d_pool[i] = 0.f;
    if (i < Gg) d_poolcnt[i] = 0.f;
}

__global__ void pool_k(const int* __restrict__ batch) {
    int gt = blockIdx.x * blockDim.x + threadIdx.x;
    int n = gt >> 5, lane = gt & 31;
    if (n >= Nn) return;
    int g = batch[n];
    const float* hr = d_h + (size_t)n * 256;
#pragma unroll
    for (int q = lane; q < 64; q += 32) {
        float4 v = *(const float4*)(hr + (q << 2));
        atomicAdd(&d_pool[g * 256 + (q << 2) + 0], v.x);
        atomicAdd(&d_pool[g * 256 + (q << 2) + 1], v.y);
        atomicAdd(&d_pool[g * 256 + (q << 2) + 2], v.z);
        atomicAdd(&d_pool[g * 256 + (q << 2) + 3], v.w);
    }
    if (lane == 0) atomicAdd(&d_poolcnt[g], 1.0f);
}

__global__ void mlp_k(const float* __restrict__ meta,
                      const float* __restrict__ l1w, const float* __restrict__ l1b,
                      const float* __restrict__ l2w, const float* __restrict__ l2b,
                      float* __restrict__ out) {
    int g = blockIdx.x;
    int t = threadIdx.x;  // 128
    __shared__ float feat[294];
    __shared__ float red[128];
    float icnt = 1.0f / fmaxf(d_poolcnt[g], 1.0f);
    for (int c = t; c < 294; c += 128)
        feat[c] = (c < 256) ? d_pool[g * 256 + c] * icnt : meta[g * 38 + (c - 256)];
    __syncthreads();
    float val = 0.f;
    if (t < 100) {
        float a = l1b[t];
        for (int i = 0; i < 294; i++) a += feat[i] * l1w[i * 100 + t];
        val = a * l2w[t];
    }
    red[t] = val;
    __syncthreads();
    for (int s = 64; s > 0; s >>= 1) {
        if (t < s) red[t] += red[t + s];
        __syncthreads();
    }
    if (t == 0) out[g] = red[0] + l2b[0];
}

// ---------------- host launcher (graph-capturable, alloc-free) ----------------
extern "C" void kernel_launch(void* const* d_in, const int* in_sizes, int n_in,
                              void* d_out, int out_size) {
    const float* x    = (const float*)d_in[0];
    const int*   eidx = (const int*)d_in[2];
    const int*   srcp = eidx;
    const int*   dstp = eidx + Ee;
    const int*   et   = (const int*)d_in[3];
    const float* meta = (const float*)d_in[4];
    const int*   bat  = (const int*)d_in[5];

    // CSR build (structure-only, once per call)
    zero_ptr_k<<<(SEGS + 1 + 255) / 256, 256>>>();
    count_k<<<(Ee + 255) / 256, 256>>>(et, dstp);
    scan1_k<<<SCAN_BLKS, 256>>>();
    scan2_k<<<1, 256>>>();
    scan3_k<<<SCAN_BLKS, 256>>>();
    cursor_k<<<(SEGS + 255) / 256, 256>>>();
    fillcol_k<<<(Ee + 255) / 256, 256>>>(srcp, dstp, et);

    copy_x_k<<<(Nn * 128 / 4 + 255) / 256, 256>>>(x);

    const int dins[4]  = {128, 100, 256, 256};
    const int douts[4] = {100, 256, 256, 256};

    for (int l = 0; l < 4; l++) {
        int din = dins[l], dout = douts[l], K = 4 * din;
        const float* W   = (const float*)d_in[6 + 5 * l];
        const float* Rw  = (const float*)d_in[7 + 5 * l];
        const float* bia = (const float*)d_in[8 + 5 * l];
        const float* gam = (const float*)d_in[9 + 5 * l];
        const float* bet = (const float*)d_in[10 + 5 * l];

        fillh_k<<<(Nn * (din / 4) + 255) / 256, 256>>>(din, K);
        gather_k<<<(SEGS * 32 + 255) / 256, 256>>>(din, K);
        gemm_k<<<dim3((Nn + 127) / 128, (dout + 127) / 128), 256>>>(Rw, W, bia, K, din, dout);
        zero_stat_k<<<1, 512>>>();
        stats_k<<<512, 256>>>(dout);
        prep_bn_k<<<1, 256>>>(gam, bet, dout);
        norm_k<<<((Nn * dout) / 4 + 255) / 256, 256>>>(dout);
    }

    zero_pool_k<<<(Gg * 256 + 255) / 256, 256>>>();
    pool_k<<<(Nn * 32 + 255) / 256, 256>>>(bat);
    mlp_k<<<Gg, 128>>>(meta, (const float*)d_in[26], (const float*)d_in[27],
                       (const float*)d_in[28], (const float*)d_in[29], (float*)d_out);
}